// round 11
// baseline (speedup 1.0000x reference)
#include <cuda_runtime.h>
#include <cuda_bf16.h>
#include <cstdint>

// ---------------- problem constants ----------------
#define RNN_B 256
#define RNN_T 256
#define RNN_I 5
#define RNN_H 2048
#define RNN_O 4

#define GRID_CTAS 128
#define NTHREADS  512      // w0-7 GEMM, w8-11 producers, w12-15 softmax

// GEMM decomposition: 32 j-tiles (64 rows) x 4 k-slices (512 k)
#define JT_ROWS 64
#define KSLICE  512
#define NKSL    4
#define KC      32         // k per chunk (double buffered)
#define NCH     16         // KSLICE / KC
#define NJ      16         // epilogue rows per CTA

#define F_ALPHA 0.1f
#define F_BETA  0.9f

// SMEM row pads (bank-conflict-free LDSM)
#define W_PITCH 520        // halfwords per Wrec row
#define H_PITCH 40         // halfwords per h row

// ---------------- shared memory layout (bytes) ----------------
#define WH_OFF   0                                   // 64*520*2 = 66560
#define WL_OFF   (WH_OFF + JT_ROWS * W_PITCH * 2)
#define HS_OFF   (WL_OFF + JT_ROWS * W_PITCH * 2)    // 133120
#define HS_BUF_STRIDE (2 * RNN_B * H_PITCH * 2)      // 40960 (hi+lo)
#define HS_ARR_STRIDE (RNN_B * H_PITCH * 2)          // 20480
#define WIN_OFF  (HS_OFF + 2 * HS_BUF_STRIDE)        // 215040 (320)
#define LOG_OFF  (WIN_OFF + NJ * RNN_I * 4)          // 215360 (32)
#define BASE_OFF (LOG_OFF + 32)                      // hbase[32] + hsum_base
#define SMEM_BYTES (BASE_OFF + 33 * 4)

#define HID_ELEMS ((size_t)RNN_B * RNN_T * RNN_H)

// ---------------- global scratch (static; no allocation) ----------------
static __device__ __nv_bfloat16 g_hhi[2 * RNN_B * RNN_H];   // [par][b][k]
static __device__ __nv_bfloat16 g_hlo[2 * RNN_B * RNN_H];
static __device__ float pre_part[NKSL * RNN_H * RNN_B];     // [ks][j][b]
static __device__ unsigned g_count;
static __device__ unsigned g_release;
static __device__ unsigned g_grp[32];       // partials-ready (per jt group)
static __device__ unsigned g_hflag[GRID_CTAS]; // per-CTA h(t) written
static __device__ unsigned g_rdone;         // producers finished reads (per step per CTA)
static __device__ unsigned g_epi[32];       // group epilogue done (partials WAR)
static __device__ unsigned g_hsum;          // aggregate epilogue count (softmax gate)

// ---------------- helpers ----------------
__device__ __forceinline__ void cp_async16(void* dst, const void* src) {
    uint32_t sa = (uint32_t)__cvta_generic_to_shared(dst);
    asm volatile("cp.async.cg.shared.global [%0], [%1], 16;\n" :: "r"(sa), "l"(src) : "memory");
}
#define CP_COMMIT() asm volatile("cp.async.commit_group;\n" ::: "memory")
#define CP_WAIT0()  asm volatile("cp.async.wait_group 0;\n" ::: "memory")
#define BAR_GEMM()  asm volatile("bar.sync 2, 384;" ::: "memory")
#define BAR_SMAX()  asm volatile("bar.sync 1, 128;" ::: "memory")
#define BAR_REL()   asm volatile("bar.sync 3, 256;" ::: "memory")

__device__ __forceinline__ void grid_barrier() {
    __syncthreads();
    __threadfence();
    if (threadIdx.x == 0) {
        volatile unsigned* relp = (volatile unsigned*)&g_release;
        unsigned rel  = *relp;
        unsigned prev = atomicAdd(&g_count, 1u);
        if (prev == (unsigned)(GRID_CTAS - 1)) {
            atomicExch(&g_count, 0u);
            __threadfence();
            atomicAdd(&g_release, 1u);
        } else {
            while (*relp == rel) { }
        }
    }
    __syncthreads();
    __threadfence();
}

#define MMA_BF16(d, a0, a1, a2, a3, b0, b1)                                   \
    asm volatile("mma.sync.aligned.m16n8k16.row.col.f32.bf16.bf16.f32 "       \
                 "{%0,%1,%2,%3}, {%4,%5,%6,%7}, {%8,%9}, {%0,%1,%2,%3};"      \
                 : "+f"((d)[0]), "+f"((d)[1]), "+f"((d)[2]), "+f"((d)[3])     \
                 : "r"(a0), "r"(a1), "r"(a2), "r"(a3), "r"(b0), "r"(b1))

#define LDSM4(r, addr)                                                         \
    asm volatile("ldmatrix.sync.aligned.m8n8.x4.shared.b16 {%0,%1,%2,%3}, [%4];" \
                 : "=r"((r)[0]), "=r"((r)[1]), "=r"((r)[2]), "=r"((r)[3])      \
                 : "r"(addr))

// producers: wait until both owner CTAs of chunk ch have published h(t-1)
__device__ __forceinline__ void wait_owner(const unsigned* hbase_s, int ks32,
                                           int ch, unsigned need) {
    if (need == 0) return;
    volatile unsigned* f0 = (volatile unsigned*)&g_hflag[ks32 + 2 * ch];
    volatile unsigned* f1 = f0 + 1;
    const unsigned b0 = hbase_s[2 * ch], b1 = hbase_s[2 * ch + 1];
    while ((*f0 - b0) < need) { }
    while ((*f1 - b1) < need) { }
    __threadfence();
}

// producers (warps 8-11, ptid 0..127): load one 32-k chunk of h hi+lo
__device__ __forceinline__ void load_chunk(char* smem, int slot,
                                           const __nv_bfloat16* ghi,
                                           const __nv_bfloat16* glo,
                                           int K0, int ch, int ptid) {
    char* dh = smem + HS_OFF + slot * HS_BUF_STRIDE;
    char* dl = dh + HS_ARR_STRIDE;
    const int kel = K0 + ch * KC;
    for (int i = ptid; i < 1024; i += 128) {    // 256 rows * 4 x 16B
        int b = i >> 2, q = i & 3;
        cp_async16(dh + b * (H_PITCH * 2) + q * 16, ghi + (size_t)b * RNN_H + kel + q * 8);
        cp_async16(dl + b * (H_PITCH * 2) + q * 16, glo + (size_t)b * RNN_H + kel + q * 8);
    }
    CP_COMMIT();
}

// ---------------- persistent kernel ----------------
__global__ void __launch_bounds__(NTHREADS, 1)
rnn_persistent_kernel(const float* __restrict__ x,     // [B,T,I]
                      const float* __restrict__ Win,   // [H,I]
                      const float* __restrict__ Wrec,  // [H,H]
                      const float* __restrict__ Wout,  // [O,H]
                      const float* __restrict__ noise, // [T,B,H]
                      float* __restrict__ out)         // hiddens [B,T,H] ++ outputs [B,T,O]
{
    extern __shared__ char smem[];
    __nv_bfloat16* Whi_s = (__nv_bfloat16*)(smem + WH_OFF);
    __nv_bfloat16* Wlo_s = (__nv_bfloat16*)(smem + WL_OFF);
    float* Win_s     = (float*)(smem + WIN_OFF);
    float* logits_s  = (float*)(smem + LOG_OFF);
    unsigned* hbase_s = (unsigned*)(smem + BASE_OFF);   // [32] owner-flag bases
    unsigned* misc_s  = hbase_s + 32;                   // [0] = hsum base

    const int tid  = threadIdx.x;
    const int lane = tid & 31;
    const int w    = tid >> 5;
    const int c    = blockIdx.x;

    const int jt = c >> 2;              // j-tile 0..31
    const int ks = c & 3;               // k-slice 0..3
    const int K0 = ks * KSLICE;
    const int ks32 = ks * 32;           // first owner CTA of this k-slice
    const int jc = c * NJ;              // epilogue row base
    const int grp = c >> 2;             // jt group

    // GEMM warp tile: 32j x 64b  (2 m-tiles x 8 n-frags), LDSM addressing
    const int jw = (w & 1) * 32;
    const int bw = (w >> 1) * 64;       // valid for w<8
    const int a_row = lane >> 2;

    const uint32_t smem_u32 = (uint32_t)__cvta_generic_to_shared(smem);
    const uint32_t a_lds_b = (uint32_t)((((lane & 15) * W_PITCH) + ((lane >> 4) << 3)) << 1);
    const uint32_t b_lds_b = (uint32_t)((((bw + (lane & 7) + ((lane >> 4) << 3)) * H_PITCH)
                                         + (((lane >> 3) & 1) << 3)) << 1);
    const uint32_t aw_hi0 = smem_u32 + WH_OFF + (uint32_t)(jw * W_PITCH * 2) + a_lds_b;
    const uint32_t aw_lo0 = smem_u32 + WL_OFF + (uint32_t)(jw * W_PITCH * 2) + a_lds_b;

    // ---- one-time: split Wrec slice into SMEM bf16 hi/lo ----
    for (int i = tid; i < JT_ROWS * KSLICE; i += NTHREADS) {
        int jl = i >> 9, kk = i & (KSLICE - 1);
        float wv = Wrec[(size_t)(jt * JT_ROWS + jl) * RNN_H + K0 + kk];
        __nv_bfloat16 hi = __float2bfloat16_rn(wv);
        __nv_bfloat16 lo = __float2bfloat16_rn(wv - __bfloat162float(hi));
        Whi_s[jl * W_PITCH + kk] = hi;
        Wlo_s[jl * W_PITCH + kk] = lo;
    }
    for (int i = tid; i < NJ * RNN_I; i += NTHREADS) Win_s[i] = Win[jc * RNN_I + i];
    {   // zero h parity 0 (owned contiguous slice)
        uint32_t* ph = (uint32_t*)g_hhi;
        uint32_t* pl = (uint32_t*)g_hlo;
        for (int i = tid; i < 2048; i += NTHREADS) { ph[c * 2048 + i] = 0u; pl[c * 2048 + i] = 0u; }
    }

    // epilogue role: thread owns (b = tid>>1, 8 rows starting at (tid&1)*8)
    const int eb   = tid >> 1;
    const int ejl0 = (tid & 1) * 8;
    float hprev[8];
    #pragma unroll
    for (int i = 0; i < 8; ++i) hprev[i] = 0.0f;

    // ---- monotonic-counter bases (read BEFORE initial barrier; replay-safe) ----
    if (tid < 32) hbase_s[tid] = *(volatile unsigned*)&g_hflag[ks32 + tid];
    unsigned grp_base = 0, rdone_base = 0, epi_base = 0;
    if (tid == 0) {
        grp_base   = *(volatile unsigned*)&g_grp[grp];
        rdone_base = *(volatile unsigned*)&g_rdone;
        epi_base   = *(volatile unsigned*)&g_epi[grp];
        misc_s[0]  = *(volatile unsigned*)&g_hsum;
    }

    grid_barrier();   // h parity 0 + Wrec smem + bases visible

    for (int t = 0; t < RNN_T; ++t) {
        const int rpar = t & 1;
        const __nv_bfloat16* ghi = g_hhi + (size_t)rpar * RNN_B * RNN_H;
        const __nv_bfloat16* glo = g_hlo + (size_t)rpar * RNN_B * RNN_H;
        const unsigned tneed = (unsigned)t;

        if (w < 12) {
            // ================= GEMM + producer path =================
            float acc[2][8][4];
            if (w < 8) {
                #pragma unroll
                for (int mi = 0; mi < 2; ++mi)
                    #pragma unroll
                    for (int nf = 0; nf < 8; ++nf)
                        #pragma unroll
                        for (int q = 0; q < 4; ++q) acc[mi][nf][q] = 0.0f;
            } else {
                wait_owner(hbase_s, ks32, 0, tneed);       // h(t-1) rows of chunk 0
                load_chunk(smem, 0, ghi, glo, K0, 0, tid - 256);
                CP_WAIT0();
            }
            BAR_GEMM();   // buf0 ready

            for (int ch = 0; ch < NCH; ++ch) {
                if (w < 8) {
                    const uint32_t hhi_u = smem_u32 + HS_OFF + (uint32_t)((ch & 1) * HS_BUF_STRIDE) + b_lds_b;
                    const uint32_t hlo_u = hhi_u + HS_ARR_STRIDE;
                    #pragma unroll
                    for (int kk = 0; kk < KC; kk += 16) {
                        const uint32_t ka2 = (uint32_t)((ch * KC + kk) << 1);
                        uint32_t ah[2][4], al[2][4];
                        LDSM4(ah[0], aw_hi0 + ka2);
                        LDSM4(ah[1], aw_hi0 + (uint32_t)(16 * W_PITCH * 2) + ka2);
                        LDSM4(al[0], aw_lo0 + ka2);
                        LDSM4(al[1], aw_lo0 + (uint32_t)(16 * W_PITCH * 2) + ka2);
                        #pragma unroll
                        for (int p = 0; p < 4; ++p) {
                            const uint32_t bo = (uint32_t)(((p * 16 * H_PITCH) + kk) << 1);
                            uint32_t bh[4], bl[4];
                            LDSM4(bh, hhi_u + bo);
                            LDSM4(bl, hlo_u + bo);
                            #pragma unroll
                            for (int mi = 0; mi < 2; ++mi) {
                                MMA_BF16(acc[mi][2*p],   ah[mi][0], ah[mi][1], ah[mi][2], ah[mi][3], bh[0], bh[1]);
                                MMA_BF16(acc[mi][2*p],   ah[mi][0], ah[mi][1], ah[mi][2], ah[mi][3], bl[0], bl[1]);
                                MMA_BF16(acc[mi][2*p],   al[mi][0], al[mi][1], al[mi][2], al[mi][3], bh[0], bh[1]);
                                MMA_BF16(acc[mi][2*p+1], ah[mi][0], ah[mi][1], ah[mi][2], ah[mi][3], bh[2], bh[3]);
                                MMA_BF16(acc[mi][2*p+1], ah[mi][0], ah[mi][1], ah[mi][2], ah[mi][3], bl[2], bl[3]);
                                MMA_BF16(acc[mi][2*p+1], al[mi][0], al[mi][1], al[mi][2], al[mi][3], bh[2], bh[3]);
                            }
                        }
                    }
                } else {
                    if (ch + 1 < NCH) {
                        wait_owner(hbase_s, ks32, ch + 1, tneed);
                        load_chunk(smem, (ch + 1) & 1, ghi, glo, K0, ch + 1, tid - 256);
                        CP_WAIT0();
                    }
                }
                BAR_GEMM();   // buf[(ch+1)&1] ready; GEMM done with buf[ch&1]
            }

            if (w < 8) {
                // ---- partials WAR: group epilogues of step t-1 must be done ----
                if (tid == 0 && t > 0) {
                    volatile unsigned* ep = (volatile unsigned*)&g_epi[grp];
                    while ((*ep - epi_base) < 4u * tneed) { }
                }
                BAR_REL();
                // ---- partial store ----
                #pragma unroll
                for (int mi = 0; mi < 2; ++mi) {
                    const int j0 = jt * JT_ROWS + jw + mi * 16 + a_row;
                    #pragma unroll
                    for (int nf = 0; nf < 8; ++nf) {
                        const int bg = bw + nf * 8 + (lane & 3) * 2;
                        float2 v0 = make_float2(acc[mi][nf][0], acc[mi][nf][1]);
                        float2 v1 = make_float2(acc[mi][nf][2], acc[mi][nf][3]);
                        *(float2*)&pre_part[((size_t)ks * RNN_H + j0    ) * RNN_B + bg] = v0;
                        *(float2*)&pre_part[((size_t)ks * RNN_H + j0 + 8) * RNN_B + bg] = v1;
                    }
                }
                __threadfence();
                BAR_REL();
                if (tid == 0) atomicAdd(&g_grp[grp], 1u);   // partials(t) ready
            } else {
                // producers: all reads of h buffer (par) for step t complete
                if (tid == 256) atomicAdd(&g_rdone, 1u);
            }
        } else if (t > 0) {
            // ================= softmax path (warps 12-15) =================
            {   // wait: all CTAs' epilogue(t-1) h rows in `out`
                volatile unsigned* hs = (volatile unsigned*)&g_hsum;
                const unsigned hb = misc_s[0];
                while ((*hs - hb) < 128u * tneed) { }
                __threadfence();
            }
            const int tp = t - 1;
            const int b0 = 2 * c;
            const int wq = w - 12;
            const int bb = wq >> 1;
            const int b  = b0 + bb;
            const int o0 = 2 * (wq & 1);
            const float* hrow = out + ((size_t)b * RNN_T + tp) * RNN_H;
            const float* w0 = Wout + (size_t)o0 * RNN_H;
            const float* w1 = Wout + (size_t)(o0 + 1) * RNN_H;
            float a0 = 0.f, a1 = 0.f;
            #pragma unroll 4
            for (int k = lane; k < RNN_H; k += 32) {
                float hv = __ldcg(hrow + k);
                a0 += hv * w0[k];
                a1 += hv * w1[k];
            }
            #pragma unroll
            for (int s = 16; s; s >>= 1) {
                a0 += __shfl_xor_sync(0xffffffffu, a0, s);
                a1 += __shfl_xor_sync(0xffffffffu, a1, s);
            }
            if (lane == 0) { logits_s[bb * 4 + o0] = a0; logits_s[bb * 4 + o0 + 1] = a1; }
            BAR_SMAX();
            if (tid - 384 < 2) {
                const int bt = tid - 384;
                float l0 = logits_s[bt * 4 + 0], l1 = logits_s[bt * 4 + 1];
                float l2 = logits_s[bt * 4 + 2], l3 = logits_s[bt * 4 + 3];
                float mx = fmaxf(fmaxf(l0, l1), fmaxf(l2, l3));
                float e0 = expf(l0 - mx), e1 = expf(l1 - mx), e2 = expf(l2 - mx), e3 = expf(l3 - mx);
                float inv = 1.0f / (e0 + e1 + e2 + e3);
                size_t base = HID_ELEMS + ((size_t)(b0 + bt) * RNN_T + tp) * RNN_O;
                out[base + 0] = e0 * inv; out[base + 1] = e1 * inv;
                out[base + 2] = e2 * inv; out[base + 3] = e3 * inv;
            }
        }

        // ---- epilogue inputs: LDGs into regs before the spin ----
        float nz[8];
        *(float4*)&nz[0] = __ldcs((const float4*)(noise + ((size_t)t * RNN_B + eb) * RNN_H + jc + ejl0));
        *(float4*)&nz[4] = __ldcs((const float4*)(noise + ((size_t)t * RNN_B + eb) * RNN_H + jc + ejl0 + 4));
        float xv[RNN_I];
        #pragma unroll
        for (int ii = 0; ii < RNN_I; ++ii)
            xv[ii] = __ldg(&x[((size_t)eb * RNN_T + t) * RNN_I + ii]);

        // ---- wait: group partials(t) ready + h-buffer WAR (readers of t-1 done) ----
        if (tid == 0) {
            volatile unsigned* gp = (volatile unsigned*)&g_grp[grp];
            while ((*gp - grp_base) < 4u * (unsigned)(t + 1)) { }
            volatile unsigned* rp = (volatile unsigned*)&g_rdone;
            while ((*rp - rdone_base) < 128u * tneed) { }
        }
        __syncthreads();
        __threadfence();

        // ---- leaky update (all 512 threads, 8 rows each), direct stores ----
        {
            float hn8[8];
            #pragma unroll
            for (int jl = 0; jl < 8; ++jl) {
                const int j = ejl0 + jl;
                const size_t pbase = (size_t)(jc + j) * RNN_B + eb;
                float pre = __ldcg(&pre_part[0 * (size_t)RNN_H * RNN_B + pbase])
                          + __ldcg(&pre_part[1 * (size_t)RNN_H * RNN_B + pbase])
                          + __ldcg(&pre_part[2 * (size_t)RNN_H * RNN_B + pbase])
                          + __ldcg(&pre_part[3 * (size_t)RNN_H * RNN_B + pbase]);
                float itv = 0.0f;
                #pragma unroll
                for (int ii = 0; ii < RNN_I; ++ii)
                    itv += xv[ii] * Win_s[j * RNN_I + ii];
                pre += itv + nz[jl];
                float hn = F_ALPHA * fmaxf(pre, 0.0f) + F_BETA * hprev[jl];
                hprev[jl] = hn;
                hn8[jl] = hn;
            }
            float* orow = out + ((size_t)eb * RNN_T + t) * RNN_H + jc + ejl0;
            *(float4*)(orow + 0) = make_float4(hn8[0], hn8[1], hn8[2], hn8[3]);
            *(float4*)(orow + 4) = make_float4(hn8[4], hn8[5], hn8[6], hn8[7]);
            const int wpar = rpar ^ 1;
            __nv_bfloat16* dhi = g_hhi + (size_t)wpar * RNN_B * RNN_H + (size_t)eb * RNN_H + jc + ejl0;
            __nv_bfloat16* dlo = g_hlo + (size_t)wpar * RNN_B * RNN_H + (size_t)eb * RNN_H + jc + ejl0;
            uint32_t hp[4], lp[4];
            #pragma unroll
            for (int q = 0; q < 4; ++q) {
                __nv_bfloat162 h2 = __floats2bfloat162_rn(hn8[2*q], hn8[2*q+1]);
                float rx = hn8[2*q]   - __low2float(h2);
                float ry = hn8[2*q+1] - __high2float(h2);
                __nv_bfloat162 l2v = __floats2bfloat162_rn(rx, ry);
                hp[q] = *(uint32_t*)&h2;
                lp[q] = *(uint32_t*)&l2v;
            }
            *(uint4*)dhi = make_uint4(hp[0], hp[1], hp[2], hp[3]);
            *(uint4*)dlo = make_uint4(lp[0], lp[1], lp[2], lp[3]);
        }

        // ---- publish h(t): fence, converge, single release per counter ----
        __threadfence();
        __syncthreads();
        if (tid == 0) {
            atomicAdd(&g_hflag[c], 1u);     // owners' flag for producers
            atomicAdd(&g_hsum, 1u);         // aggregate for softmax
            atomicAdd(&g_epi[grp], 1u);     // partials(t) reads done (WAR release)
        }
    }

    // ---- final softmax for t = T-1 (warps 12-15) ----
    if (w >= 12) {
        {   // wait: all epilogues of step T-1 published
            volatile unsigned* hs = (volatile unsigned*)&g_hsum;
            const unsigned hb = misc_s[0];
            while ((*hs - hb) < 128u * (unsigned)RNN_T) { }
            __threadfence();
        }
        const int tp = RNN_T - 1;
        const int b0 = 2 * c;
        const int wq = w - 12;
        const int bb = wq >> 1;
        const int b  = b0 + bb;
        const int o0 = 2 * (wq & 1);
        const float* hrow = out + ((size_t)b * RNN_T + tp) * RNN_H;
        const float* w0 = Wout + (size_t)o0 * RNN_H;
        const float* w1 = Wout + (size_t)(o0 + 1) * RNN_H;
        float a0 = 0.f, a1 = 0.f;
        #pragma unroll 4
        for (int k = lane; k < RNN_H; k += 32) {
            float hv = __ldcg(hrow + k);
            a0 += hv * w0[k];
            a1 += hv * w1[k];
        }
        #pragma unroll
        for (int s = 16; s; s >>= 1) {
            a0 += __shfl_xor_sync(0xffffffffu, a0, s);
            a1 += __shfl_xor_sync(0xffffffffu, a1, s);
        }
        if (lane == 0) { logits_s[bb * 4 + o0] = a0; logits_s[bb * 4 + o0 + 1] = a1; }
        BAR_SMAX();
        if (tid - 384 < 2) {
            const int bt = tid - 384;
            float l0 = logits_s[bt * 4 + 0], l1 = logits_s[bt * 4 + 1];
            float l2 = logits_s[bt * 4 + 2], l3 = logits_s[bt * 4 + 3];
            float mx = fmaxf(fmaxf(l0, l1), fmaxf(l2, l3));
            float e0 = expf(l0 - mx), e1 = expf(l1 - mx), e2 = expf(l2 - mx), e3 = expf(l3 - mx);
            float inv = 1.0f / (e0 + e1 + e2 + e3);
            size_t base = HID_ELEMS + ((size_t)(b0 + bt) * RNN_T + tp) * RNN_O;
            out[base + 0] = e0 * inv; out[base + 1] = e1 * inv;
            out[base + 2] = e2 * inv; out[base + 3] = e3 * inv;
        }
    }
}

// ---------------- launch ----------------
extern "C" void kernel_launch(void* const* d_in, const int* in_sizes, int n_in,
                              void* d_out, int out_size) {
    const float* x     = (const float*)d_in[0];
    const float* Win   = (const float*)d_in[1];
    const float* Wrec  = (const float*)d_in[2];
    const float* Wout  = (const float*)d_in[3];
    const float* noise = (const float*)d_in[4];
    float* out = (float*)d_out;

    cudaFuncSetAttribute(rnn_persistent_kernel,
                         cudaFuncAttributeMaxDynamicSharedMemorySize, SMEM_BYTES);
    rnn_persistent_kernel<<<GRID_CTAS, NTHREADS, SMEM_BYTES>>>(x, Win, Wrec, Wout, noise, out);
}

// round 16
// speedup vs baseline: 1.3746x; 1.3746x over previous
#include <cuda_runtime.h>
#include <cuda_bf16.h>
#include <cstdint>

// ---------------- problem constants ----------------
#define RNN_B 256
#define RNN_T 256
#define RNN_I 5
#define RNN_H 2048
#define RNN_O 4

#define GRID_CTAS 128
#define NTHREADS  512      // w0-7 GEMM, w8-11 producers, w12-15 softmax

// GEMM decomposition: 32 j-tiles (64 rows) x 4 k-slices (512 k)
#define JT_ROWS 64
#define KSLICE  512
#define NKSL    4
#define KC      32         // k per chunk (double buffered)
#define NCH     16         // KSLICE / KC
#define NJ      16         // epilogue rows per CTA

#define F_ALPHA 0.1f
#define F_BETA  0.9f

// SMEM row pads (bank-conflict-free LDSM)
#define W_PITCH 520        // halfwords per Wrec row
#define H_PITCH 40         // halfwords per h row

// ---------------- shared memory layout (bytes) ----------------
#define WH_OFF   0                                   // 64*520*2 = 66560
#define WL_OFF   (WH_OFF + JT_ROWS * W_PITCH * 2)
#define HS_OFF   (WL_OFF + JT_ROWS * W_PITCH * 2)    // 133120
#define HS_BUF_STRIDE (2 * RNN_B * H_PITCH * 2)      // 40960 (hi+lo)
#define HS_ARR_STRIDE (RNN_B * H_PITCH * 2)          // 20480
#define WIN_OFF  (HS_OFF + 2 * HS_BUF_STRIDE)        // 215040 (320)
#define LOG_OFF  (WIN_OFF + NJ * RNN_I * 4)          // 215360 (32)
#define HB_OFF   (LOG_OFF + 32)                      // hbase[128]
#define RB_OFF   (HB_OFF + 128 * 4)                  // rbase[32]
#define MS_OFF   (RB_OFF + 32 * 4)                   // misc[2]
#define SMEM_BYTES (MS_OFF + 8)

#define HID_ELEMS ((size_t)RNN_B * RNN_T * RNN_H)

// ---------------- global scratch (static; no allocation) ----------------
static __device__ __nv_bfloat16 g_hhi[2 * RNN_B * RNN_H];   // [par][b][k]
static __device__ __nv_bfloat16 g_hlo[2 * RNN_B * RNN_H];
static __device__ float pre_part[NKSL * RNN_H * RNN_B];     // [ks][j][b]
static __device__ unsigned g_count;
static __device__ unsigned g_release;
static __device__ unsigned g_grp[32];          // group partials-ready
static __device__ unsigned g_epi[32];          // group epilogues-done (partials WAR)
static __device__ unsigned g_hflag[GRID_CTAS]; // per-CTA: epilogue/h(t) published
static __device__ unsigned g_rflag[GRID_CTAS]; // per-CTA: producer h-reads done

// ---------------- helpers ----------------
__device__ __forceinline__ void cp_async16(void* dst, const void* src) {
    uint32_t sa = (uint32_t)__cvta_generic_to_shared(dst);
    asm volatile("cp.async.cg.shared.global [%0], [%1], 16;\n" :: "r"(sa), "l"(src) : "memory");
}
#define CP_COMMIT() asm volatile("cp.async.commit_group;\n" ::: "memory")
#define CP_WAIT0()  asm volatile("cp.async.wait_group 0;\n" ::: "memory")
#define BAR_GEMM()  asm volatile("bar.sync 2, 384;" ::: "memory")
#define BAR_SMAX()  asm volatile("bar.sync 1, 128;" ::: "memory")
#define BAR_REL()   asm volatile("bar.sync 3, 256;" ::: "memory")

__device__ __forceinline__ void grid_barrier() {
    __syncthreads();
    __threadfence();
    if (threadIdx.x == 0) {
        volatile unsigned* relp = (volatile unsigned*)&g_release;
        unsigned rel  = *relp;
        unsigned prev = atomicAdd(&g_count, 1u);
        if (prev == (unsigned)(GRID_CTAS - 1)) {
            atomicExch(&g_count, 0u);
            __threadfence();
            atomicAdd(&g_release, 1u);
        } else {
            while (*relp == rel) { }
        }
    }
    __syncthreads();
    __threadfence();
}

__device__ __forceinline__ void spin_ge(volatile unsigned* p, unsigned base, unsigned need) {
    while ((*p - base) < need) { }
}

#define MMA_BF16(d, a0, a1, a2, a3, b0, b1)                                   \
    asm volatile("mma.sync.aligned.m16n8k16.row.col.f32.bf16.bf16.f32 "       \
                 "{%0,%1,%2,%3}, {%4,%5,%6,%7}, {%8,%9}, {%0,%1,%2,%3};"      \
                 : "+f"((d)[0]), "+f"((d)[1]), "+f"((d)[2]), "+f"((d)[3])     \
                 : "r"(a0), "r"(a1), "r"(a2), "r"(a3), "r"(b0), "r"(b1))

#define LDSM4(r, addr)                                                         \
    asm volatile("ldmatrix.sync.aligned.m8n8.x4.shared.b16 {%0,%1,%2,%3}, [%4];" \
                 : "=r"((r)[0]), "=r"((r)[1]), "=r"((r)[2]), "=r"((r)[3])      \
                 : "r"(addr))

// producers (warps 8-11, ptid 0..127): load one 32-k chunk of h hi+lo
__device__ __forceinline__ void load_chunk(char* smem, int slot,
                                           const __nv_bfloat16* ghi,
                                           const __nv_bfloat16* glo,
                                           int K0, int ch, int ptid) {
    char* dh = smem + HS_OFF + slot * HS_BUF_STRIDE;
    char* dl = dh + HS_ARR_STRIDE;
    const int kel = K0 + ch * KC;
    for (int i = ptid; i < 1024; i += 128) {    // 256 rows * 4 x 16B
        int b = i >> 2, q = i & 3;
        cp_async16(dh + b * (H_PITCH * 2) + q * 16, ghi + (size_t)b * RNN_H + kel + q * 8);
        cp_async16(dl + b * (H_PITCH * 2) + q * 16, glo + (size_t)b * RNN_H + kel + q * 8);
    }
    CP_COMMIT();
}

// ---------------- persistent kernel ----------------
__global__ void __launch_bounds__(NTHREADS, 1)
rnn_persistent_kernel(const float* __restrict__ x,     // [B,T,I]
                      const float* __restrict__ Win,   // [H,I]
                      const float* __restrict__ Wrec,  // [H,H]
                      const float* __restrict__ Wout,  // [O,H]
                      const float* __restrict__ noise, // [T,B,H]
                      float* __restrict__ out)         // hiddens [B,T,H] ++ outputs [B,T,O]
{
    extern __shared__ char smem[];
    __nv_bfloat16* Whi_s = (__nv_bfloat16*)(smem + WH_OFF);
    __nv_bfloat16* Wlo_s = (__nv_bfloat16*)(smem + WL_OFF);
    float* Win_s      = (float*)(smem + WIN_OFF);
    float* logits_s   = (float*)(smem + LOG_OFF);
    unsigned* hbase_s = (unsigned*)(smem + HB_OFF);   // [128]
    unsigned* rbase_s = (unsigned*)(smem + RB_OFF);   // [32]
    unsigned* misc_s  = (unsigned*)(smem + MS_OFF);   // [0]=grp_base [1]=epi_base

    const int tid  = threadIdx.x;
    const int lane = tid & 31;
    const int w    = tid >> 5;
    const int c    = blockIdx.x;

    const int jt = c >> 2;              // j-tile 0..31
    const int ks = c & 3;               // k-slice 0..3
    const int K0 = ks * KSLICE;
    const int ks32 = ks * 32;           // writer CTAs of region ks: [32ks, 32ks+32)
    const int jc = c * NJ;              // epilogue row base
    const int grp = c >> 2;             // jt group (4 CTAs share partials)
    const int region = c >> 5;          // h-region this CTA WRITES; readers = {4m+region}

    // GEMM warp tile: 32j x 64b  (2 m-tiles x 8 n-frags), LDSM addressing
    const int jw = (w & 1) * 32;
    const int bw = (w >> 1) * 64;       // valid for w<8
    const int a_row = lane >> 2;

    const uint32_t smem_u32 = (uint32_t)__cvta_generic_to_shared(smem);
    const uint32_t a_lds_b = (uint32_t)((((lane & 15) * W_PITCH) + ((lane >> 4) << 3)) << 1);
    const uint32_t b_lds_b = (uint32_t)((((bw + (lane & 7) + ((lane >> 4) << 3)) * H_PITCH)
                                         + (((lane >> 3) & 1) << 3)) << 1);
    const uint32_t aw_hi0 = smem_u32 + WH_OFF + (uint32_t)(jw * W_PITCH * 2) + a_lds_b;
    const uint32_t aw_lo0 = smem_u32 + WL_OFF + (uint32_t)(jw * W_PITCH * 2) + a_lds_b;

    // ---- one-time: split Wrec slice into SMEM bf16 hi/lo ----
    for (int i = tid; i < JT_ROWS * KSLICE; i += NTHREADS) {
        int jl = i >> 9, kk = i & (KSLICE - 1);
        float wv = Wrec[(size_t)(jt * JT_ROWS + jl) * RNN_H + K0 + kk];
        __nv_bfloat16 hi = __float2bfloat16_rn(wv);
        __nv_bfloat16 lo = __float2bfloat16_rn(wv - __bfloat162float(hi));
        Whi_s[jl * W_PITCH + kk] = hi;
        Wlo_s[jl * W_PITCH + kk] = lo;
    }
    for (int i = tid; i < NJ * RNN_I; i += NTHREADS) Win_s[i] = Win[jc * RNN_I + i];
    {   // zero h parity 0 (owned contiguous slice)
        uint32_t* ph = (uint32_t*)g_hhi;
        uint32_t* pl = (uint32_t*)g_hlo;
        for (int i = tid; i < 2048; i += NTHREADS) { ph[c * 2048 + i] = 0u; pl[c * 2048 + i] = 0u; }
    }

    // epilogue role: thread owns (b = tid>>1, 8 rows starting at (tid&1)*8)
    const int eb   = tid >> 1;
    const int ejl0 = (tid & 1) * 8;
    float hprev[8];
    #pragma unroll
    for (int i = 0; i < 8; ++i) hprev[i] = 0.0f;

    // ---- monotonic-counter bases (read BEFORE initial barrier; replay-safe) ----
    if (tid < 128) hbase_s[tid] = *(volatile unsigned*)&g_hflag[tid];
    if (tid < 32)  rbase_s[tid] = *(volatile unsigned*)&g_rflag[4 * tid + region];
    if (tid == 0) {
        misc_s[0] = *(volatile unsigned*)&g_grp[grp];
        misc_s[1] = *(volatile unsigned*)&g_epi[grp];
    }

    grid_barrier();   // h parity 0 + Wrec smem + bases visible (only grid-wide sync)

    for (int t = 0; t < RNN_T; ++t) {
        const int rpar = t & 1;
        const __nv_bfloat16* ghi = g_hhi + (size_t)rpar * RNN_B * RNN_H;
        const __nv_bfloat16* glo = g_hlo + (size_t)rpar * RNN_B * RNN_H;
        const unsigned tneed = (unsigned)t;

        if (w < 12) {
            // ================= GEMM + producer path =================
            float acc[2][8][4];
            if (w < 8) {
                #pragma unroll
                for (int mi = 0; mi < 2; ++mi)
                    #pragma unroll
                    for (int nf = 0; nf < 8; ++nf)
                        #pragma unroll
                        for (int q = 0; q < 4; ++q) acc[mi][nf][q] = 0.0f;
            } else {
                // STEP gate (once, lane-parallel): writers of region ks published h(t-1)
                if (t > 0) {
                    spin_ge((volatile unsigned*)&g_hflag[ks32 + lane],
                            hbase_s[ks32 + lane], tneed);
                    __threadfence();
                }
                __syncwarp();
                load_chunk(smem, 0, ghi, glo, K0, 0, tid - 256);
                CP_WAIT0();
            }
            BAR_GEMM();   // buf0 ready

            for (int ch = 0; ch < NCH; ++ch) {
                if (w < 8) {
                    const uint32_t hhi_u = smem_u32 + HS_OFF + (uint32_t)((ch & 1) * HS_BUF_STRIDE) + b_lds_b;
                    const uint32_t hlo_u = hhi_u + HS_ARR_STRIDE;
                    #pragma unroll
                    for (int kk = 0; kk < KC; kk += 16) {
                        const uint32_t ka2 = (uint32_t)((ch * KC + kk) << 1);
                        uint32_t ah[2][4], al[2][4];
                        LDSM4(ah[0], aw_hi0 + ka2);
                        LDSM4(ah[1], aw_hi0 + (uint32_t)(16 * W_PITCH * 2) + ka2);
                        LDSM4(al[0], aw_lo0 + ka2);
                        LDSM4(al[1], aw_lo0 + (uint32_t)(16 * W_PITCH * 2) + ka2);
                        #pragma unroll
                        for (int p = 0; p < 4; ++p) {
                            const uint32_t bo = (uint32_t)(((p * 16 * H_PITCH) + kk) << 1);
                            uint32_t bh[4], bl[4];
                            LDSM4(bh, hhi_u + bo);
                            LDSM4(bl, hlo_u + bo);
                            #pragma unroll
                            for (int mi = 0; mi < 2; ++mi) {
                                MMA_BF16(acc[mi][2*p],   ah[mi][0], ah[mi][1], ah[mi][2], ah[mi][3], bh[0], bh[1]);
                                MMA_BF16(acc[mi][2*p],   ah[mi][0], ah[mi][1], ah[mi][2], ah[mi][3], bl[0], bl[1]);
                                MMA_BF16(acc[mi][2*p],   al[mi][0], al[mi][1], al[mi][2], al[mi][3], bh[0], bh[1]);
                                MMA_BF16(acc[mi][2*p+1], ah[mi][0], ah[mi][1], ah[mi][2], ah[mi][3], bh[2], bh[3]);
                                MMA_BF16(acc[mi][2*p+1], ah[mi][0], ah[mi][1], ah[mi][2], ah[mi][3], bl[2], bl[3]);
                                MMA_BF16(acc[mi][2*p+1], al[mi][0], al[mi][1], al[mi][2], al[mi][3], bh[2], bh[3]);
                            }
                        }
                    }
                } else {
                    if (ch + 1 < NCH) {
                        load_chunk(smem, (ch + 1) & 1, ghi, glo, K0, ch + 1, tid - 256);
                        CP_WAIT0();
                    }
                }
                BAR_GEMM();   // buf[(ch+1)&1] ready; GEMM done with buf[ch&1]
            }

            if (w < 8) {
                // partials WAR (exact, 4-wide): group epilogues(t-1) read partials(t-1)
                if (tid == 0 && t > 0)
                    spin_ge((volatile unsigned*)&g_epi[grp], misc_s[1], 4u * tneed);
                BAR_REL();
                #pragma unroll
                for (int mi = 0; mi < 2; ++mi) {
                    const int j0 = jt * JT_ROWS + jw + mi * 16 + a_row;
                    #pragma unroll
                    for (int nf = 0; nf < 8; ++nf) {
                        const int bg = bw + nf * 8 + (lane & 3) * 2;
                        float2 v0 = make_float2(acc[mi][nf][0], acc[mi][nf][1]);
                        float2 v1 = make_float2(acc[mi][nf][2], acc[mi][nf][3]);
                        *(float2*)&pre_part[((size_t)ks * RNN_H + j0    ) * RNN_B + bg] = v0;
                        *(float2*)&pre_part[((size_t)ks * RNN_H + j0 + 8) * RNN_B + bg] = v1;
                    }
                }
                __threadfence();
                BAR_REL();
                if (tid == 0) atomicAdd(&g_grp[grp], 1u);   // partials(t) ready
            } else {
                // producers: all h reads of step t complete (past final BAR_GEMM)
                if (tid == 256) atomicAdd(&g_rflag[c], 1u);
            }
        } else if (t > 0) {
            // ================= softmax path (warps 12-15) =================
            {   // exact gate: ALL 128 CTAs published h(t-1); 128 threads, 1 flag each
                const int idx = tid - 384;
                spin_ge((volatile unsigned*)&g_hflag[idx], hbase_s[idx], tneed);
                __threadfence();
            }
            BAR_SMAX();
            const int tp = t - 1;
            const int b0 = 2 * c;
            const int wq = w - 12;
            const int bb = wq >> 1;
            const int b  = b0 + bb;
            const int o0 = 2 * (wq & 1);
            const float* hrow = out + ((size_t)b * RNN_T + tp) * RNN_H;
            const float* w0 = Wout + (size_t)o0 * RNN_H;
            const float* w1 = Wout + (size_t)(o0 + 1) * RNN_H;
            float a0 = 0.f, a1 = 0.f;
            #pragma unroll 4
            for (int k = lane; k < RNN_H; k += 32) {
                float hv = __ldcg(hrow + k);
                a0 += hv * w0[k];
                a1 += hv * w1[k];
            }
            #pragma unroll
            for (int s = 16; s; s >>= 1) {
                a0 += __shfl_xor_sync(0xffffffffu, a0, s);
                a1 += __shfl_xor_sync(0xffffffffu, a1, s);
            }
            if (lane == 0) { logits_s[bb * 4 + o0] = a0; logits_s[bb * 4 + o0 + 1] = a1; }
            BAR_SMAX();
            if (tid - 384 < 2) {
                const int bt = tid - 384;
                float l0 = logits_s[bt * 4 + 0], l1 = logits_s[bt * 4 + 1];
                float l2 = logits_s[bt * 4 + 2], l3 = logits_s[bt * 4 + 3];
                float mx = fmaxf(fmaxf(l0, l1), fmaxf(l2, l3));
                float e0 = expf(l0 - mx), e1 = expf(l1 - mx), e2 = expf(l2 - mx), e3 = expf(l3 - mx);
                float inv = 1.0f / (e0 + e1 + e2 + e3);
                size_t base = HID_ELEMS + ((size_t)(b0 + bt) * RNN_T + tp) * RNN_O;
                out[base + 0] = e0 * inv; out[base + 1] = e1 * inv;
                out[base + 2] = e2 * inv; out[base + 3] = e3 * inv;
            }
        }

        // ---- epilogue inputs: LDGs into regs before the gates ----
        float nz[8];
        *(float4*)&nz[0] = __ldcs((const float4*)(noise + ((size_t)t * RNN_B + eb) * RNN_H + jc + ejl0));
        *(float4*)&nz[4] = __ldcs((const float4*)(noise + ((size_t)t * RNN_B + eb) * RNN_H + jc + ejl0 + 4));
        float xv[RNN_I];
        #pragma unroll
        for (int ii = 0; ii < RNN_I; ++ii)
            xv[ii] = __ldg(&x[((size_t)eb * RNN_T + t) * RNN_I + ii]);

        // ---- epilogue gates (lane-parallel, exact) ----
        // warp0: the 32 reader CTAs of my h-region finished step-(t-1) reads (WAR)
        if (w == 0 && t > 0)
            spin_ge((volatile unsigned*)&g_rflag[4 * lane + region], rbase_s[lane], tneed);
        // tid32: my group's partials(t) all stored
        if (tid == 32)
            spin_ge((volatile unsigned*)&g_grp[grp], misc_s[0], 4u * (unsigned)(t + 1));
        __syncthreads();
        __threadfence();

        // ---- leaky update (all 512 threads, 8 rows each), direct stores ----
        {
            float hn8[8];
            #pragma unroll
            for (int jl = 0; jl < 8; ++jl) {
                const int j = ejl0 + jl;
                const size_t pbase = (size_t)(jc + j) * RNN_B + eb;
                float pre = __ldcg(&pre_part[0 * (size_t)RNN_H * RNN_B + pbase])
                          + __ldcg(&pre_part[1 * (size_t)RNN_H * RNN_B + pbase])
                          + __ldcg(&pre_part[2 * (size_t)RNN_H * RNN_B + pbase])
                          + __ldcg(&pre_part[3 * (size_t)RNN_H * RNN_B + pbase]);
                float itv = 0.0f;
                #pragma unroll
                for (int ii = 0; ii < RNN_I; ++ii)
                    itv += xv[ii] * Win_s[j * RNN_I + ii];
                pre += itv + nz[jl];
                float hn = F_ALPHA * fmaxf(pre, 0.0f) + F_BETA * hprev[jl];
                hprev[jl] = hn;
                hn8[jl] = hn;
            }
            float* orow = out + ((size_t)eb * RNN_T + t) * RNN_H + jc + ejl0;
            *(float4*)(orow + 0) = make_float4(hn8[0], hn8[1], hn8[2], hn8[3]);
            *(float4*)(orow + 4) = make_float4(hn8[4], hn8[5], hn8[6], hn8[7]);
            const int wpar = rpar ^ 1;
            __nv_bfloat16* dhi = g_hhi + (size_t)wpar * RNN_B * RNN_H + (size_t)eb * RNN_H + jc + ejl0;
            __nv_bfloat16* dlo = g_hlo + (size_t)wpar * RNN_B * RNN_H + (size_t)eb * RNN_H + jc + ejl0;
            uint32_t hp[4], lp[4];
            #pragma unroll
            for (int q = 0; q < 4; ++q) {
                __nv_bfloat162 h2 = __floats2bfloat162_rn(hn8[2*q], hn8[2*q+1]);
                float rx = hn8[2*q]   - __low2float(h2);
                float ry = hn8[2*q+1] - __high2float(h2);
                __nv_bfloat162 l2v = __floats2bfloat162_rn(rx, ry);
                hp[q] = *(uint32_t*)&h2;
                lp[q] = *(uint32_t*)&l2v;
            }
            *(uint4*)dhi = make_uint4(hp[0], hp[1], hp[2], hp[3]);
            *(uint4*)dlo = make_uint4(lp[0], lp[1], lp[2], lp[3]);
        }

        // ---- publish h(t) + partials-read-done: fence, converge, release ----
        __threadfence();
        __syncthreads();
        if (tid == 0) {
            atomicAdd(&g_hflag[c], 1u);   // h(t) + hiddens row published
            atomicAdd(&g_epi[grp], 1u);   // partials(t) consumed (WAR release)
        }
    }

    // ---- final softmax for t = T-1 (warps 12-15) ----
    if (w >= 12) {
        {   // all CTAs published step T-1
            const int idx = tid - 384;
            spin_ge((volatile unsigned*)&g_hflag[idx], hbase_s[idx], (unsigned)RNN_T);
            __threadfence();
        }
        BAR_SMAX();
        const int tp = RNN_T - 1;
        const int b0 = 2 * c;
        const int wq = w - 12;
        const int bb = wq >> 1;
        const int b  = b0 + bb;
        const int o0 = 2 * (wq & 1);
        const float* hrow = out + ((size_t)b * RNN_T + tp) * RNN_H;
        const float* w0 = Wout + (size_t)o0 * RNN_H;
        const float* w1 = Wout + (size_t)(o0 + 1) * RNN_H;
        float a0 = 0.f, a1 = 0.f;
        #pragma unroll 4
        for (int k = lane; k < RNN_H; k += 32) {
            float hv = __ldcg(hrow + k);
            a0 += hv * w0[k];
            a1 += hv * w1[k];
        }
        #pragma unroll
        for (int s = 16; s; s >>= 1) {
            a0 += __shfl_xor_sync(0xffffffffu, a0, s);
            a1 += __shfl_xor_sync(0xffffffffu, a1, s);
        }
        if (lane == 0) { logits_s[bb * 4 + o0] = a0; logits_s[bb * 4 + o0 + 1] = a1; }
        BAR_SMAX();
        if (tid - 384 < 2) {
            const int bt = tid - 384;
            float l0 = logits_s[bt * 4 + 0], l1 = logits_s[bt * 4 + 1];
            float l2 = logits_s[bt * 4 + 2], l3 = logits_s[bt * 4 + 3];
            float mx = fmaxf(fmaxf(l0, l1), fmaxf(l2, l3));
            float e0 = expf(l0 - mx), e1 = expf(l1 - mx), e2 = expf(l2 - mx), e3 = expf(l3 - mx);
            float inv = 1.0f / (e0 + e1 + e2 + e3);
            size_t base = HID_ELEMS + ((size_t)(b0 + bt) * RNN_T + tp) * RNN_O;
            out[base + 0] = e0 * inv; out[base + 1] = e1 * inv;
            out[base + 2] = e2 * inv; out[base + 3] = e3 * inv;
        }
    }
}

// ---------------- launch ----------------
extern "C" void kernel_launch(void* const* d_in, const int* in_sizes, int n_in,
                              void* d_out, int out_size) {
    const float* x     = (const float*)d_in[0];
    const float* Win   = (const float*)d_in[1];
    const float* Wrec  = (const float*)d_in[2];
    const float* Wout  = (const float*)d_in[3];
    const float* noise = (const float*)d_in[4];
    float* out = (float*)d_out;

    cudaFuncSetAttribute(rnn_persistent_kernel,
                         cudaFuncAttributeMaxDynamicSharedMemorySize, SMEM_BYTES);
    rnn_persistent_kernel<<<GRID_CTAS, NTHREADS, SMEM_BYTES>>>(x, Win, Wrec, Wout, noise, out);
}

// round 17
// speedup vs baseline: 2.3870x; 1.7365x over previous
#include <cuda_runtime.h>
#include <cuda_fp16.h>
#include <cstdint>

// ---------------- problem constants ----------------
#define RNN_B 256
#define RNN_T 256
#define RNN_I 5
#define RNN_H 2048
#define RNN_O 4

#define GRID_CTAS 128
#define NTHREADS  512      // w0-7 GEMM, w8-11 producers, w12-15 softmax

// GEMM decomposition: 32 j-tiles (64 rows) x 4 k-slices (512 k)
#define JT_ROWS 64
#define KSLICE  512
#define NKSL    4
#define KC      64         // k per chunk (double buffered)  [R17: 32->64]
#define NCH     8          // KSLICE / KC
#define NJ      16         // epilogue rows per CTA

#define F_ALPHA 0.1f
#define F_BETA  0.9f

// SMEM row pads (bank-conflict-free LDSM)
#define W_PITCH 520        // halfwords per Wrec row (260 words ≡ 4 mod 32)
#define H_PITCH 72         // halfwords per h row (36 words ≡ 4 mod 32)

// ---------------- shared memory layout (bytes) ----------------
#define WH_OFF   0                                   // 64*520*2 = 66560 (fp16 W, single)
#define HS_OFF   (WH_OFF + JT_ROWS * W_PITCH * 2)    // 66560
#define HS_BUF_STRIDE (RNN_B * H_PITCH * 2)          // 36864 (single fp16 array)
#define WIN_OFF  (HS_OFF + 2 * HS_BUF_STRIDE)        // 140288 (320)
#define LOG_OFF  (WIN_OFF + NJ * RNN_I * 4)          // 140608 (32)
#define HB_OFF   (LOG_OFF + 32)                      // hbase[128]
#define RB_OFF   (HB_OFF + 128 * 4)                  // rbase[32]
#define MS_OFF   (RB_OFF + 32 * 4)                   // misc[2]
#define SMEM_BYTES (MS_OFF + 8)

#define HID_ELEMS ((size_t)RNN_B * RNN_T * RNN_H)

// ---------------- global scratch (static; no allocation) ----------------
static __device__ __half g_h[2 * RNN_B * RNN_H];            // [par][b][k]  fp16 state
static __device__ float pre_part[NKSL * RNN_H * RNN_B];     // [ks][j][b]
static __device__ unsigned g_count;
static __device__ unsigned g_release;
static __device__ unsigned g_grp[32];          // group partials-ready
static __device__ unsigned g_epi[32];          // group epilogues-done (partials WAR)
static __device__ unsigned g_hflag[GRID_CTAS]; // per-CTA: epilogue/h(t) published
static __device__ unsigned g_rflag[GRID_CTAS]; // per-CTA: producer h-reads done

// ---------------- helpers ----------------
__device__ __forceinline__ void cp_async16(void* dst, const void* src) {
    uint32_t sa = (uint32_t)__cvta_generic_to_shared(dst);
    asm volatile("cp.async.cg.shared.global [%0], [%1], 16;\n" :: "r"(sa), "l"(src) : "memory");
}
#define CP_COMMIT() asm volatile("cp.async.commit_group;\n" ::: "memory")
#define CP_WAIT0()  asm volatile("cp.async.wait_group 0;\n" ::: "memory")
#define BAR_GEMM()  asm volatile("bar.sync 2, 384;" ::: "memory")
#define BAR_SMAX()  asm volatile("bar.sync 1, 128;" ::: "memory")
#define BAR_REL()   asm volatile("bar.sync 3, 256;" ::: "memory")

__device__ __forceinline__ void grid_barrier() {
    __syncthreads();
    __threadfence();
    if (threadIdx.x == 0) {
        volatile unsigned* relp = (volatile unsigned*)&g_release;
        unsigned rel  = *relp;
        unsigned prev = atomicAdd(&g_count, 1u);
        if (prev == (unsigned)(GRID_CTAS - 1)) {
            atomicExch(&g_count, 0u);
            __threadfence();
            atomicAdd(&g_release, 1u);
        } else {
            while (*relp == rel) { }
        }
    }
    __syncthreads();
    __threadfence();
}

__device__ __forceinline__ void spin_ge(volatile unsigned* p, unsigned base, unsigned need) {
    while ((*p - base) < need) { }
}

#define MMA_FP16(d, a0, a1, a2, a3, b0, b1)                                   \
    asm volatile("mma.sync.aligned.m16n8k16.row.col.f32.f16.f16.f32 "         \
                 "{%0,%1,%2,%3}, {%4,%5,%6,%7}, {%8,%9}, {%0,%1,%2,%3};"      \
                 : "+f"((d)[0]), "+f"((d)[1]), "+f"((d)[2]), "+f"((d)[3])     \
                 : "r"(a0), "r"(a1), "r"(a2), "r"(a3), "r"(b0), "r"(b1))

#define LDSM4(r, addr)                                                         \
    asm volatile("ldmatrix.sync.aligned.m8n8.x4.shared.b16 {%0,%1,%2,%3}, [%4];" \
                 : "=r"((r)[0]), "=r"((r)[1]), "=r"((r)[2]), "=r"((r)[3])      \
                 : "r"(addr))

// producers (warps 8-11, ptid 0..127): load one 64-k chunk of h fp16
// chunk = 256 rows x 128 B = 2048 x 16B transfers
__device__ __forceinline__ void load_chunk(char* smem, int slot,
                                           const __half* gh,
                                           int K0, int ch, int ptid) {
    char* dh = smem + HS_OFF + slot * HS_BUF_STRIDE;
    const int kel = K0 + ch * KC;
    for (int i = ptid; i < 2048; i += 128) {
        int b = i >> 3, q = i & 7;
        cp_async16(dh + b * (H_PITCH * 2) + q * 16, gh + (size_t)b * RNN_H + kel + q * 8);
    }
    CP_COMMIT();
}

// ---------------- persistent kernel ----------------
__global__ void __launch_bounds__(NTHREADS, 1)
rnn_persistent_kernel(const float* __restrict__ x,     // [B,T,I]
                      const float* __restrict__ Win,   // [H,I]
                      const float* __restrict__ Wrec,  // [H,H]
                      const float* __restrict__ Wout,  // [O,H]
                      const float* __restrict__ noise, // [T,B,H]
                      float* __restrict__ out)         // hiddens [B,T,H] ++ outputs [B,T,O]
{
    extern __shared__ char smem[];
    __half* Wh_s      = (__half*)(smem + WH_OFF);
    float* Win_s      = (float*)(smem + WIN_OFF);
    float* logits_s   = (float*)(smem + LOG_OFF);
    unsigned* hbase_s = (unsigned*)(smem + HB_OFF);   // [128]
    unsigned* rbase_s = (unsigned*)(smem + RB_OFF);   // [32]
    unsigned* misc_s  = (unsigned*)(smem + MS_OFF);   // [0]=grp_base [1]=epi_base

    const int tid  = threadIdx.x;
    const int lane = tid & 31;
    const int w    = tid >> 5;
    const int c    = blockIdx.x;

    const int jt = c >> 2;              // j-tile 0..31
    const int ks = c & 3;               // k-slice 0..3
    const int K0 = ks * KSLICE;
    const int ks32 = ks * 32;           // writer CTAs of region ks: [32ks, 32ks+32)
    const int jc = c * NJ;              // epilogue row base
    const int grp = c >> 2;             // jt group (4 CTAs share partials)
    const int region = c >> 5;          // h-region this CTA WRITES; readers = {4m+region}

    // GEMM warp tile: 32j x 64b  (2 m-tiles x 8 n-frags), LDSM addressing
    const int jw = (w & 1) * 32;
    const int bw = (w >> 1) * 64;       // valid for w<8
    const int a_row = lane >> 2;

    const uint32_t smem_u32 = (uint32_t)__cvta_generic_to_shared(smem);
    const uint32_t a_lds_b = (uint32_t)((((lane & 15) * W_PITCH) + ((lane >> 4) << 3)) << 1);
    const uint32_t b_lds_b = (uint32_t)((((bw + (lane & 7) + ((lane >> 4) << 3)) * H_PITCH)
                                         + (((lane >> 3) & 1) << 3)) << 1);
    const uint32_t aw0 = smem_u32 + WH_OFF + (uint32_t)(jw * W_PITCH * 2) + a_lds_b;

    // ---- one-time: Wrec slice -> SMEM fp16 (single-pass precision) ----
    for (int i = tid; i < JT_ROWS * KSLICE; i += NTHREADS) {
        int jl = i >> 9, kk = i & (KSLICE - 1);
        float wv = Wrec[(size_t)(jt * JT_ROWS + jl) * RNN_H + K0 + kk];
        Wh_s[jl * W_PITCH + kk] = __float2half_rn(wv);
    }
    for (int i = tid; i < NJ * RNN_I; i += NTHREADS) Win_s[i] = Win[jc * RNN_I + i];
    {   // zero h parity 0 (owned contiguous slice: 2048 u32 per CTA)
        uint32_t* ph = (uint32_t*)g_h;
        for (int i = tid; i < 2048; i += NTHREADS) ph[c * 2048 + i] = 0u;
    }

    // epilogue role: thread owns (b = tid>>1, 8 rows starting at (tid&1)*8)
    const int eb   = tid >> 1;
    const int ejl0 = (tid & 1) * 8;
    float hprev[8];
    #pragma unroll
    for (int i = 0; i < 8; ++i) hprev[i] = 0.0f;

    // ---- monotonic-counter bases (read BEFORE initial barrier; replay-safe) ----
    if (tid < 128) hbase_s[tid] = *(volatile unsigned*)&g_hflag[tid];
    if (tid < 32)  rbase_s[tid] = *(volatile unsigned*)&g_rflag[4 * tid + region];
    if (tid == 0) {
        misc_s[0] = *(volatile unsigned*)&g_grp[grp];
        misc_s[1] = *(volatile unsigned*)&g_epi[grp];
    }

    grid_barrier();   // h parity 0 + Wrec smem + bases visible (only grid-wide sync)

    for (int t = 0; t < RNN_T; ++t) {
        const int rpar = t & 1;
        const __half* gh = g_h + (size_t)rpar * RNN_B * RNN_H;
        const unsigned tneed = (unsigned)t;

        if (w < 12) {
            // ================= GEMM + producer path =================
            float acc[2][8][4];
            if (w < 8) {
                #pragma unroll
                for (int mi = 0; mi < 2; ++mi)
                    #pragma unroll
                    for (int nf = 0; nf < 8; ++nf)
                        #pragma unroll
                        for (int q = 0; q < 4; ++q) acc[mi][nf][q] = 0.0f;
            } else {
                // STEP gate (once, lane-parallel): writers of region ks published h(t-1)
                if (t > 0) {
                    spin_ge((volatile unsigned*)&g_hflag[ks32 + lane],
                            hbase_s[ks32 + lane], tneed);
                    __threadfence();
                }
                __syncwarp();
                load_chunk(smem, 0, gh, K0, 0, tid - 256);
                CP_WAIT0();
            }
            BAR_GEMM();   // buf0 ready

            for (int ch = 0; ch < NCH; ++ch) {
                if (w < 8) {
                    const uint32_t hh_u = smem_u32 + HS_OFF + (uint32_t)((ch & 1) * HS_BUF_STRIDE) + b_lds_b;
                    #pragma unroll
                    for (int kk = 0; kk < KC; kk += 16) {
                        const uint32_t ka2 = (uint32_t)((ch * KC + kk) << 1);
                        uint32_t ah[2][4];
                        LDSM4(ah[0], aw0 + ka2);
                        LDSM4(ah[1], aw0 + (uint32_t)(16 * W_PITCH * 2) + ka2);
                        #pragma unroll
                        for (int p = 0; p < 4; ++p) {
                            const uint32_t bo = (uint32_t)(((p * 16 * H_PITCH) + kk) << 1);
                            uint32_t bh[4];
                            LDSM4(bh, hh_u + bo);
                            #pragma unroll
                            for (int mi = 0; mi < 2; ++mi) {
                                MMA_FP16(acc[mi][2*p],   ah[mi][0], ah[mi][1], ah[mi][2], ah[mi][3], bh[0], bh[1]);
                                MMA_FP16(acc[mi][2*p+1], ah[mi][0], ah[mi][1], ah[mi][2], ah[mi][3], bh[2], bh[3]);
                            }
                        }
                    }
                } else {
                    if (ch + 1 < NCH) {
                        load_chunk(smem, (ch + 1) & 1, gh, K0, ch + 1, tid - 256);
                        CP_WAIT0();
                    }
                }
                BAR_GEMM();   // buf[(ch+1)&1] ready; GEMM done with buf[ch&1]
            }

            if (w < 8) {
                // partials WAR (exact, 4-wide): group epilogues(t-1) read partials(t-1)
                if (tid == 0 && t > 0)
                    spin_ge((volatile unsigned*)&g_epi[grp], misc_s[1], 4u * tneed);
                BAR_REL();
                #pragma unroll
                for (int mi = 0; mi < 2; ++mi) {
                    const int j0 = jt * JT_ROWS + jw + mi * 16 + a_row;
                    #pragma unroll
                    for (int nf = 0; nf < 8; ++nf) {
                        const int bg = bw + nf * 8 + (lane & 3) * 2;
                        float2 v0 = make_float2(acc[mi][nf][0], acc[mi][nf][1]);
                        float2 v1 = make_float2(acc[mi][nf][2], acc[mi][nf][3]);
                        *(float2*)&pre_part[((size_t)ks * RNN_H + j0    ) * RNN_B + bg] = v0;
                        *(float2*)&pre_part[((size_t)ks * RNN_H + j0 + 8) * RNN_B + bg] = v1;
                    }
                }
                __threadfence();
                BAR_REL();
                if (tid == 0) atomicAdd(&g_grp[grp], 1u);   // partials(t) ready
            } else {
                // producers: all h reads of step t complete (past final BAR_GEMM)
                if (tid == 256) atomicAdd(&g_rflag[c], 1u);
            }
        } else if (t > 0) {
            // ================= softmax path (warps 12-15) =================
            {   // exact gate: ALL 128 CTAs published h(t-1); 128 threads, 1 flag each
                const int idx = tid - 384;
                spin_ge((volatile unsigned*)&g_hflag[idx], hbase_s[idx], tneed);
                __threadfence();
            }
            BAR_SMAX();
            const int tp = t - 1;
            const int b0 = 2 * c;
            const int wq = w - 12;
            const int bb = wq >> 1;
            const int b  = b0 + bb;
            const int o0 = 2 * (wq & 1);
            const float* hrow = out + ((size_t)b * RNN_T + tp) * RNN_H;
            const float* w0 = Wout + (size_t)o0 * RNN_H;
            const float* w1 = Wout + (size_t)(o0 + 1) * RNN_H;
            float a0 = 0.f, a1 = 0.f;
            #pragma unroll 4
            for (int k = lane; k < RNN_H; k += 32) {
                float hv = __ldcg(hrow + k);
                a0 += hv * w0[k];
                a1 += hv * w1[k];
            }
            #pragma unroll
            for (int s = 16; s; s >>= 1) {
                a0 += __shfl_xor_sync(0xffffffffu, a0, s);
                a1 += __shfl_xor_sync(0xffffffffu, a1, s);
            }
            if (lane == 0) { logits_s[bb * 4 + o0] = a0; logits_s[bb * 4 + o0 + 1] = a1; }
            BAR_SMAX();
            if (tid - 384 < 2) {
                const int bt = tid - 384;
                float l0 = logits_s[bt * 4 + 0], l1 = logits_s[bt * 4 + 1];
                float l2 = logits_s[bt * 4 + 2], l3 = logits_s[bt * 4 + 3];
                float mx = fmaxf(fmaxf(l0, l1), fmaxf(l2, l3));
                float e0 = expf(l0 - mx), e1 = expf(l1 - mx), e2 = expf(l2 - mx), e3 = expf(l3 - mx);
                float inv = 1.0f / (e0 + e1 + e2 + e3);
                size_t base = HID_ELEMS + ((size_t)(b0 + bt) * RNN_T + tp) * RNN_O;
                out[base + 0] = e0 * inv; out[base + 1] = e1 * inv;
                out[base + 2] = e2 * inv; out[base + 3] = e3 * inv;
            }
        }

        // ---- epilogue inputs: LDGs into regs before the gates ----
        float nz[8];
        *(float4*)&nz[0] = __ldcs((const float4*)(noise + ((size_t)t * RNN_B + eb) * RNN_H + jc + ejl0));
        *(float4*)&nz[4] = __ldcs((const float4*)(noise + ((size_t)t * RNN_B + eb) * RNN_H + jc + ejl0 + 4));
        float xv[RNN_I];
        #pragma unroll
        for (int ii = 0; ii < RNN_I; ++ii)
            xv[ii] = __ldg(&x[((size_t)eb * RNN_T + t) * RNN_I + ii]);

        // ---- epilogue gates (lane-parallel, exact) ----
        // warp0: the 32 reader CTAs of my h-region finished step-(t-1) reads (WAR)
        if (w == 0 && t > 0)
            spin_ge((volatile unsigned*)&g_rflag[4 * lane + region], rbase_s[lane], tneed);
        // tid32: my group's partials(t) all stored
        if (tid == 32)
            spin_ge((volatile unsigned*)&g_grp[grp], misc_s[0], 4u * (unsigned)(t + 1));
        __syncthreads();
        __threadfence();

        // ---- leaky update (all 512 threads, 8 rows each), direct stores ----
        {
            float hn8[8];
            #pragma unroll
            for (int jl = 0; jl < 8; ++jl) {
                const int j = ejl0 + jl;
                const size_t pbase = (size_t)(jc + j) * RNN_B + eb;
                float pre = __ldcg(&pre_part[0 * (size_t)RNN_H * RNN_B + pbase])
                          + __ldcg(&pre_part[1 * (size_t)RNN_H * RNN_B + pbase])
                          + __ldcg(&pre_part[2 * (size_t)RNN_H * RNN_B + pbase])
                          + __ldcg(&pre_part[3 * (size_t)RNN_H * RNN_B + pbase]);
                float itv = 0.0f;
                #pragma unroll
                for (int ii = 0; ii < RNN_I; ++ii)
                    itv += xv[ii] * Win_s[j * RNN_I + ii];
                pre += itv + nz[jl];
                float hn = F_ALPHA * fmaxf(pre, 0.0f) + F_BETA * hprev[jl];
                hprev[jl] = hn;
                hn8[jl] = hn;
            }
            float* orow = out + ((size_t)eb * RNN_T + t) * RNN_H + jc + ejl0;
            *(float4*)(orow + 0) = make_float4(hn8[0], hn8[1], hn8[2], hn8[3]);
            *(float4*)(orow + 4) = make_float4(hn8[4], hn8[5], hn8[6], hn8[7]);
            // fp16 state (16B per thread)
            const int wpar = rpar ^ 1;
            __half* dh = g_h + (size_t)wpar * RNN_B * RNN_H + (size_t)eb * RNN_H + jc + ejl0;
            uint32_t hp[4];
            #pragma unroll
            for (int q = 0; q < 4; ++q) {
                __half2 h2 = __float22half2_rn(make_float2(hn8[2*q], hn8[2*q+1]));
                hp[q] = *(uint32_t*)&h2;
            }
            *(uint4*)dh = make_uint4(hp[0], hp[1], hp[2], hp[3]);
        }

        // ---- publish h(t) + partials-read-done: fence, converge, release ----
        __threadfence();
        __syncthreads();
        if (tid == 0) {
            atomicAdd(&g_hflag[c], 1u);   // h(t) + hiddens row published
            atomicAdd(&g_epi[grp], 1u);   // partials(t) consumed (WAR release)
        }
    }

    // ---- final softmax for t = T-1 (warps 12-15) ----
    if (w >= 12) {
        {   // all CTAs published step T-1
            const int idx = tid - 384;
            spin_ge((volatile unsigned*)&g_hflag[idx], hbase_s[idx], (unsigned)RNN_T);
            __threadfence();
        }
        BAR_SMAX();
        const int tp = RNN_T - 1;
        const int b0 = 2 * c;
        const int wq = w - 12;
        const int bb = wq >> 1;
        const int b  = b0 + bb;
        const int o0 = 2 * (wq & 1);
        const float* hrow = out + ((size_t)b * RNN_T + tp) * RNN_H;
        const float* w0 = Wout + (size_t)o0 * RNN_H;
        const float* w1 = Wout + (size_t)(o0 + 1) * RNN_H;
        float a0 = 0.f, a1 = 0.f;
        #pragma unroll 4
        for (int k = lane; k < RNN_H; k += 32) {
            float hv = __ldcg(hrow + k);
            a0 += hv * w0[k];
            a1 += hv * w1[k];
        }
        #pragma unroll
        for (int s = 16; s; s >>= 1) {
            a0 += __shfl_xor_sync(0xffffffffu, a0, s);
            a1 += __shfl_xor_sync(0xffffffffu, a1, s);
        }
        if (lane == 0) { logits_s[bb * 4 + o0] = a0; logits_s[bb * 4 + o0 + 1] = a1; }
        BAR_SMAX();
        if (tid - 384 < 2) {
            const int bt = tid - 384;
            float l0 = logits_s[bt * 4 + 0], l1 = logits_s[bt * 4 + 1];
            float l2 = logits_s[bt * 4 + 2], l3 = logits_s[bt * 4 + 3];
            float mx = fmaxf(fmaxf(l0, l1), fmaxf(l2, l3));
            float e0 = expf(l0 - mx), e1 = expf(l1 - mx), e2 = expf(l2 - mx), e3 = expf(l3 - mx);
            float inv = 1.0f / (e0 + e1 + e2 + e3);
            size_t base = HID_ELEMS + ((size_t)(b0 + bt) * RNN_T + tp) * RNN_O;
            out[base + 0] = e0 * inv; out[base + 1] = e1 * inv;
            out[base + 2] = e2 * inv; out[base + 3] = e3 * inv;
        }
    }
}

// ---------------- launch ----------------
extern "C" void kernel_launch(void* const* d_in, const int* in_sizes, int n_in,
                              void* d_out, int out_size) {
    const float* x     = (const float*)d_in[0];
    const float* Win   = (const float*)d_in[1];
    const float* Wrec  = (const float*)d_in[2];
    const float* Wout  = (const float*)d_in[3];
    const float* noise = (const float*)d_in[4];
    float* out = (float*)d_out;

    cudaFuncSetAttribute(rnn_persistent_kernel,
                         cudaFuncAttributeMaxDynamicSharedMemorySize, SMEM_BYTES);
    rnn_persistent_kernel<<<GRID_CTAS, NTHREADS, SMEM_BYTES>>>(x, Win, Wrec, Wout, noise, out);
}